// round 13
// baseline (speedup 1.0000x reference)
#include <cuda_runtime.h>
#include <cuda_bf16.h>

// ALiBi bias materialization:
//   out[z, i, j] = -slopes[z % 16] * |i - j|
//   z in [0, 64)  (h = z % 16), i, j in [0, 2048)
// Output: 64 * 2048 * 2048 fp32 = 1 GiB -> pure HBM-write-bound.
//
// FINAL (12-round characterization). Kernel-internal 144.3us = 7.03 TB/s
// at 86% DRAM duty — the write wall on this part; wall-clock 146.9-147.6us
// including fixed replay overhead. All axes swept and neutral:
//   store width 128/256-bit | cache policy default/.cs/.wt
//   block 256/512/1024 | rows/block 1/2/4 | grid 32768-262144
//   occupancy 48-90% (no BW effect)
// Rejected: persistent grid (-21%, serializes store issue).
// Config: 512 threads, 2 rows/block (head uniform, 2 | 2048), one
// independent STG.128 per thread per row, grid 65536.

#define S        2048
#define NUM_H    16
#define Z_TOTAL  64
#define THREADS  512
#define ROWS_PER_BLOCK 2

__global__ __launch_bounds__(THREADS)
void alibi_kernel(const float* __restrict__ slopes, float* __restrict__ out) {
    const unsigned row0 = blockIdx.x * ROWS_PER_BLOCK;   // [0, 131072) step 2
    const unsigned h    = (row0 >> 11) & (NUM_H - 1);    // z % 16, block-uniform

    const float neg_slope = -__ldg(&slopes[h]);

    const unsigned j0 = threadIdx.x * 4u;
    const float fj = (float)j0;

    float* base = out + (size_t)row0 * S + j0;

#pragma unroll
    for (int r = 0; r < ROWS_PER_BLOCK; r++) {
        const float fi = (float)((row0 + r) & (S - 1));

        float4 v;
        v.x = neg_slope * fabsf(fi - fj);
        v.y = neg_slope * fabsf(fi - (fj + 1.0f));
        v.z = neg_slope * fabsf(fi - (fj + 2.0f));
        v.w = neg_slope * fabsf(fi - (fj + 3.0f));

        *reinterpret_cast<float4*>(base + (size_t)r * S) = v;
    }
}

extern "C" void kernel_launch(void* const* d_in, const int* in_sizes, int n_in,
                              void* d_out, int out_size) {
    const float* slopes = (const float*)d_in[0];
    float* out = (float*)d_out;

    const unsigned grid = (Z_TOTAL * S) / ROWS_PER_BLOCK;   // 65536
    alibi_kernel<<<grid, THREADS>>>(slopes, out);
}

// round 14
// speedup vs baseline: 1.0070x; 1.0070x over previous
#include <cuda_runtime.h>
#include <cuda_bf16.h>

// ALiBi bias materialization:
//   out[z, i, j] = -slopes[z % 16] * |i - j|
//   z in [0, 64)  (h = z % 16), i, j in [0, 2048)
// Output: 64 * 2048 * 2048 fp32 = 1 GiB -> pure HBM-write-bound.
//
// FINAL (13-round characterization). Kernel-internal 144.3us = 7.03 TB/s
// at 86% DRAM duty — the pure-write ceiling of this HBM3e part. Wall
// 146.9-147.4us (fixed ~2.5us graph-replay overhead + /-0.3us noise).
// Swept neutral: store width 128/256b; policy default/.cs/.wt; block
// 256/512/1024; rows/block 1/2/4; grid 32768-262144; occ 48-90%.
// Rejected: persistent grid (-21%).
// Config: 512 threads, 2 rows/block (head uniform, 2 | 2048), one
// independent STG.128 per thread per row, grid 65536.

#define S        2048
#define NUM_H    16
#define Z_TOTAL  64
#define THREADS  512
#define ROWS_PER_BLOCK 2

__global__ __launch_bounds__(THREADS)
void alibi_kernel(const float* __restrict__ slopes, float* __restrict__ out) {
    const unsigned row0 = blockIdx.x * ROWS_PER_BLOCK;   // [0, 131072) step 2
    const unsigned h    = (row0 >> 11) & (NUM_H - 1);    // z % 16, block-uniform

    const float neg_slope = -__ldg(&slopes[h]);

    const unsigned j0 = threadIdx.x * 4u;
    const float fj = (float)j0;

    float* base = out + (size_t)row0 * S + j0;

#pragma unroll
    for (int r = 0; r < ROWS_PER_BLOCK; r++) {
        const float fi = (float)((row0 + r) & (S - 1));

        float4 v;
        v.x = neg_slope * fabsf(fi - fj);
        v.y = neg_slope * fabsf(fi - (fj + 1.0f));
        v.z = neg_slope * fabsf(fi - (fj + 2.0f));
        v.w = neg_slope * fabsf(fi - (fj + 3.0f));

        *reinterpret_cast<float4*>(base + (size_t)r * S) = v;
    }
}

extern "C" void kernel_launch(void* const* d_in, const int* in_sizes, int n_in,
                              void* d_out, int out_size) {
    const float* slopes = (const float*)d_in[0];
    float* out = (float*)d_out;

    const unsigned grid = (Z_TOTAL * S) / ROWS_PER_BLOCK;   // 65536
    alibi_kernel<<<grid, THREADS>>>(slopes, out);
}